// round 4
// baseline (speedup 1.0000x reference)
#include <cuda_runtime.h>
#include <cstdint>

typedef unsigned long long u64;

#define TOKENS   2048
#define IN_DIM   1024
#define OUT_DIM  512
#define RANK     32
#define NTG      32        // T*G
#define NCELL    128
#define TILE_TOK 128
#define OC       32        // outputs per block
#define CELLF    1060      // floats per staged cell tile: 33 rows x 32 + 4 pad
#define BUFF     (4*CELLF) // one tg buffer (4 cells) in floats

// ---------------- scratch (static device globals: allocation-free) ----------
__device__ __align__(16) float         g_z[TOKENS * RANK];
__device__ __align__(16) unsigned char g_win[TOKENS * NTG];

// ---------------- helpers ----------------------------------------------------
__device__ __forceinline__ u64 dup2(float v) {
    u64 r; asm("mov.b64 %0, {%1, %1};" : "=l"(r) : "f"(v)); return r;
}
__device__ __forceinline__ void ffma2(u64& d, u64 a, u64 b) {
    asm("fma.rn.f32x2 %0, %1, %2, %0;" : "+l"(d) : "l"(a), "l"(b));
}
__device__ __forceinline__ float2 u2f(u64 v) {
    float2 r; asm("mov.b64 {%0, %1}, %2;" : "=f"(r.x), "=f"(r.y) : "l"(v)); return r;
}

// =============================================================================
// Kernel 1: z projection + routing argmin.  512 blocks x 256 thr, 4 tokens/blk.
// =============================================================================
__global__ __launch_bounds__(256) void kRoute(
    const float* __restrict__ x, const float* __restrict__ proj_w,
    const float* __restrict__ router_w, const float* __restrict__ router_b) {
    __shared__ __align__(16) float xs[4][IN_DIM];   // 16 KB
    __shared__ float zs[4][RANK];

    const int tid  = threadIdx.x;
    const int tok0 = blockIdx.x * 4;

    {   // stage 4 token rows of x (coalesced float4)
        const float4* xg  = (const float4*)(x + (size_t)tok0 * IN_DIM);
        float4*       xs4 = (float4*)xs;
#pragma unroll
        for (int i = 0; i < 4; i++) xs4[tid + 256 * i] = xg[tid + 256 * i];
    }
    __syncthreads();

    const int w = tid >> 5, lane = tid & 31;
    float acc[4][4];   // [j][t]
#pragma unroll
    for (int j = 0; j < 4; j++)
#pragma unroll
        for (int t = 0; t < 4; t++) acc[j][t] = 0.f;

#pragma unroll 8
    for (int m = 0; m < 32; m++) {
        const int i = lane + 32 * m;
        float wv[4];
#pragma unroll
        for (int j = 0; j < 4; j++)
            wv[j] = __ldg(&proj_w[(size_t)(w * 4 + j) * IN_DIM + i]);
#pragma unroll
        for (int t = 0; t < 4; t++) {
            const float xv = xs[t][i];
#pragma unroll
            for (int j = 0; j < 4; j++) acc[j][t] += wv[j] * xv;
        }
    }
#pragma unroll
    for (int j = 0; j < 4; j++)
#pragma unroll
        for (int t = 0; t < 4; t++) {
            float s = acc[j][t];
#pragma unroll
            for (int off = 16; off > 0; off >>= 1)
                s += __shfl_xor_sync(0xffffffffu, s, off);
            if (lane == 0) {
                zs[t][w * 4 + j] = s;
                g_z[(size_t)(tok0 + t) * RANK + w * 4 + j] = s;
            }
        }
    __syncthreads();

    // scores (fp32); thread = (token t, tg). first-min argmin -> winner k.
    if (tid < 128) {
        const int t  = tid >> 5;
        const int tg = tid & 31;
        const float* rw = router_w + (size_t)tg * 4 * RANK;
        const float* rb = router_b + (size_t)tg * 4;
        float s[4];
#pragma unroll
        for (int k = 0; k < 4; k++) s[k] = rb[k];
#pragma unroll 8
        for (int r = 0; r < RANK; r++) {
            const float zr = zs[t][r];
#pragma unroll
            for (int k = 0; k < 4; k++)
                s[k] += zr * rw[k * RANK + r];
        }
        int best = 0; float bv = s[0];
#pragma unroll
        for (int k = 1; k < 4; k++)
            if (s[k] < bv) { bv = s[k]; best = k; }
        g_win[(size_t)(tok0 + t) * NTG + tg] = (unsigned char)best;
    }
}

// =============================================================================
// Kernel 2: selected affine apply.
// Grid (16 token tiles, 16 out-chunks of 32) x 128 threads.
// Lane owns 1 token x 32 outs; acc (16 u64) and z (33 f32) live in registers
// for the whole kernel. Per tg: cp.async-stage 4 cell tiles (bias folded as
// row 32), each lane streams its winner cell's weights.
// =============================================================================
__device__ __forceinline__ void stage_tg(
    const float* __restrict__ aw, const float* __restrict__ ab,
    int oc, int tg, int buf, int tid, uint32_t wt0) {
    const int c0 = tg * 4;
    for (int s = tid; s < 4 * 33 * 8; s += 128) {
        const int c   = s / 264;
        const int rem = s - c * 264;
        const int r   = rem >> 3, j = rem & 7;
        const float* src = (r < 32)
            ? aw + (((size_t)(c0 + c) * RANK + r) * OUT_DIM + oc + j * 4)
            : ab + ((size_t)(c0 + c) * OUT_DIM + oc + j * 4);
        const uint32_t dst =
            wt0 + (uint32_t)((buf * BUFF + c * CELLF + r * 32 + j * 4) * 4);
        asm volatile("cp.async.ca.shared.global [%0], [%1], 16;"
                     :: "r"(dst), "l"(src));
    }
    asm volatile("cp.async.commit_group;" ::: "memory");
}

__global__ __launch_bounds__(128) void kApply(
    const float* __restrict__ aw, const float* __restrict__ ab,
    float* __restrict__ out) {
    __shared__ __align__(16) float wt[2 * BUFF];   // 33.9 KB
    const int tid = threadIdx.x;
    const int t   = blockIdx.x * TILE_TOK + tid;   // this lane's token
    const int oc  = blockIdx.y * OC;
    const uint32_t wt0 = (uint32_t)__cvta_generic_to_shared(wt);

    // z into registers (once), z[32] = 1 pairs with the bias row
    float zr[33];
    {
        const float4* zp = (const float4*)(g_z + (size_t)t * RANK);
#pragma unroll
        for (int j = 0; j < 8; j++) {
            float4 v = __ldg(zp + j);
            zr[4 * j] = v.x; zr[4 * j + 1] = v.y;
            zr[4 * j + 2] = v.z; zr[4 * j + 3] = v.w;
        }
        zr[32] = 1.0f;
    }

    u64 acc[16];
#pragma unroll
    for (int i = 0; i < 16; i++) acc[i] = 0ull;

    const unsigned char* winp = g_win + (size_t)t * NTG;

    stage_tg(aw, ab, oc, 0, 0, tid, wt0);

    for (int tg = 0; tg < NTG; tg++) {
        if (tg + 1 < NTG) {
            stage_tg(aw, ab, oc, tg + 1, (tg + 1) & 1, tid, wt0);
            asm volatile("cp.async.wait_group 1;" ::: "memory");
        } else {
            asm volatile("cp.async.wait_group 0;" ::: "memory");
        }
        __syncthreads();

        const int cell = winp[tg];
        const uint32_t base =
            wt0 + (uint32_t)(((tg & 1) * BUFF + cell * CELLF) * 4);
#pragma unroll
        for (int r = 0; r < 33; r++) {
            const u64 zd = dup2(zr[r]);
#pragma unroll
            for (int j = 0; j < 8; j++) {
                u64 w01, w23;
                asm("ld.shared.v2.b64 {%0, %1}, [%2];"
                    : "=l"(w01), "=l"(w23)
                    : "r"(base + (uint32_t)(r * 128 + j * 16)));
                ffma2(acc[2 * j],     zd, w01);
                ffma2(acc[2 * j + 1], zd, w23);
            }
        }
        __syncthreads();   // compute done before next iteration re-stages buf
    }

    // epilogue: scale + store (each (t, oc-range) owned exclusively)
    const float S = 0.17677669529663687f;   // 1/sqrt(32)
    float* op = out + (size_t)t * OUT_DIM + oc;
#pragma unroll
    for (int j = 0; j < 8; j++) {
        const float2 a = u2f(acc[2 * j]), b = u2f(acc[2 * j + 1]);
        float4 v;
        v.x = a.x * S; v.y = a.y * S; v.z = b.x * S; v.w = b.y * S;
        ((float4*)op)[j] = v;
    }
}

// =============================================================================
extern "C" void kernel_launch(void* const* d_in, const int* in_sizes, int n_in,
                              void* d_out, int out_size) {
    const float* x   = (const float*)d_in[0];
    const float* pw  = (const float*)d_in[1];
    const float* rw  = (const float*)d_in[2];
    const float* rb  = (const float*)d_in[3];
    const float* aw  = (const float*)d_in[4];
    const float* ab  = (const float*)d_in[5];
    float*       out = (float*)d_out;

    kRoute<<<TOKENS / 4, 256>>>(x, pw, rw, rb);
    kApply<<<dim3(TOKENS / TILE_TOK, OUT_DIM / OC), 128>>>(aw, ab, out);
}

// round 5
// speedup vs baseline: 1.5361x; 1.5361x over previous
#include <cuda_runtime.h>
#include <cstdint>

typedef unsigned long long u64;
typedef unsigned int u32;

#define TOKENS   2048
#define IN_DIM   1024
#define OUT_DIM  512
#define RANK     32
#define NTG      32
#define NTILE    16
#define TILE_TOK 128
#define OC       64
#define MAXIT    640
#define WROW     68              // floats per weight row (64 + 4 pad)
#define WCELL    (33*WROW)       // 2244 floats per cell (32 w rows + bias row)
#define WBUF     (4*WCELL)       // 8976 floats per tg buffer
#define ZROW     136             // 128 tokens + 8 dummy cols
#define ACCS     68

// ---------------- scratch (static device globals: allocation-free) ----------
__device__ __align__(16) float         g_z[TOKENS * RANK];
__device__ __align__(16) unsigned char g_win[TOKENS * NTG];
__device__ __align__(16) u64           g_itok[NTILE * MAXIT];
__device__ u32                         g_imeta[NTILE * MAXIT];
__device__ int                         g_nit[NTILE];

// ---------------- helpers ----------------------------------------------------
__device__ __forceinline__ u64 dup2(float v) {
    u64 r; asm("mov.b64 %0, {%1, %1};" : "=l"(r) : "f"(v)); return r;
}
__device__ __forceinline__ void ffma2(u64& d, u64 a, u64 b) {
    asm("fma.rn.f32x2 %0, %1, %2, %0;" : "+l"(d) : "l"(a), "l"(b));
}
__device__ __forceinline__ float2 u2f(u64 v) {
    float2 r; asm("mov.b64 {%0, %1}, %2;" : "=f"(r.x), "=f"(r.y) : "l"(v)); return r;
}

// =============================================================================
// Kernel 1: z projection + routing argmin.  512 blocks x 256 thr, 4 tokens/blk.
// router_w staged in smem (bank-safe) -- fixes the uncoalesced-LDG storm.
// =============================================================================
__global__ __launch_bounds__(256) void kRoute(
    const float* __restrict__ x, const float* __restrict__ proj_w,
    const float* __restrict__ router_w, const float* __restrict__ router_b) {
    __shared__ __align__(16) float xs[4][IN_DIM];
    __shared__ float zs[4][RANK];
    __shared__ float rw_s[NTG][129];   // [tg][k*32+r], stride 129 (bank-safe)
    __shared__ float rb_s[128];

    const int tid  = threadIdx.x;
    const int tok0 = blockIdx.x * 4;

    {   // stage x (4 token rows, coalesced float4)
        const float4* xg  = (const float4*)(x + (size_t)tok0 * IN_DIM);
        float4*       xs4 = (float4*)xs;
#pragma unroll
        for (int i = 0; i < 4; i++) xs4[tid + 256 * i] = xg[tid + 256 * i];
    }
    {   // stage router_w (4096 floats) coalesced, scatter into padded rows
#pragma unroll
        for (int e = tid; e < 1024; e += 256) {
            const float4 v = ((const float4*)router_w)[e];
            const int tg = e >> 5, w4 = e & 31;
            float* d = &rw_s[tg][(w4 >> 3) * 32 + (w4 & 7) * 4];
            d[0] = v.x; d[1] = v.y; d[2] = v.z; d[3] = v.w;
        }
        if (tid < 128) rb_s[tid] = router_b[tid];
    }
    __syncthreads();

    const int w = tid >> 5, lane = tid & 31;
    float acc[4][4];
#pragma unroll
    for (int j = 0; j < 4; j++)
#pragma unroll
        for (int t = 0; t < 4; t++) acc[j][t] = 0.f;

#pragma unroll 8
    for (int m = 0; m < 32; m++) {
        const int i = lane + 32 * m;
        float wv[4];
#pragma unroll
        for (int j = 0; j < 4; j++)
            wv[j] = __ldg(&proj_w[(size_t)(w * 4 + j) * IN_DIM + i]);
#pragma unroll
        for (int t = 0; t < 4; t++) {
            const float xv = xs[t][i];
#pragma unroll
            for (int j = 0; j < 4; j++) acc[j][t] += wv[j] * xv;
        }
    }
#pragma unroll
    for (int j = 0; j < 4; j++)
#pragma unroll
        for (int t = 0; t < 4; t++) {
            float s = acc[j][t];
#pragma unroll
            for (int off = 16; off > 0; off >>= 1)
                s += __shfl_xor_sync(0xffffffffu, s, off);
            if (lane == 0) {
                zs[t][w * 4 + j] = s;
                g_z[(size_t)(tok0 + t) * RANK + w * 4 + j] = s;
            }
        }
    __syncthreads();

    if (tid < 128) {
        const int t  = tid >> 5;
        const int tg = tid & 31;
        float s[4];
#pragma unroll
        for (int k = 0; k < 4; k++) s[k] = rb_s[tg * 4 + k];
#pragma unroll 8
        for (int r = 0; r < RANK; r++) {
            const float zr = zs[t][r];
#pragma unroll
            for (int k = 0; k < 4; k++) s[k] += zr * rw_s[tg][k * 32 + r];
        }
        int best = 0; float bv = s[0];
#pragma unroll
        for (int k = 1; k < 4; k++)
            if (s[k] < bv) { bv = s[k]; best = k; }
        g_win[(size_t)(tok0 + t) * NTG + tg] = (unsigned char)best;
    }
}

// =============================================================================
// Kernel 2: per-tile cell sort -> flat item list (tg-ordered).
// 16 blocks x 128 thr.  Item = 8 same-cell tokens (u64) + meta (cell | tg<<8).
// Dummy token = 128 pads cells to 8; items/tg in [16,19].
// =============================================================================
__global__ __launch_bounds__(128) void kSort() {
    __shared__ unsigned char win_t[NTG][132];
    __shared__ unsigned char ord[NTG][160];
    __shared__ unsigned char offp[NTG][5];
    __shared__ int it_cnt[NTG];
    __shared__ int it_off[NTG + 1];
    __shared__ u64 s_itok[MAXIT];
    __shared__ u32 s_imeta[MAXIT];

    const int tid   = threadIdx.x;
    const int tile0 = blockIdx.x * TILE_TOK;

    {   // transpose win: [tok][tg] -> win_t[tg][tok]
        const u32* wp = (const u32*)(g_win + (size_t)(tile0 + tid) * NTG);
#pragma unroll
        for (int q = 0; q < 8; q++) {
            const u32 v = wp[q];
            win_t[q * 4 + 0][tid] = (unsigned char)(v);
            win_t[q * 4 + 1][tid] = (unsigned char)(v >> 8);
            win_t[q * 4 + 2][tid] = (unsigned char)(v >> 16);
            win_t[q * 4 + 3][tid] = (unsigned char)(v >> 24);
        }
    }
    __syncthreads();

    if (tid < NTG) {
        const int tg = tid;
        int cnt[4] = {0, 0, 0, 0};
        for (int t = 0; t < TILE_TOK; t++) cnt[win_t[tg][t]]++;
        int o[5]; o[0] = 0;
#pragma unroll
        for (int c = 0; c < 4; c++) o[c + 1] = o[c] + ((cnt[c] + 7) & ~7);
        int pos[4];
#pragma unroll
        for (int c = 0; c < 4; c++) pos[c] = o[c];
        for (int t = 0; t < TILE_TOK; t++) {
            const int c = win_t[tg][t];
            ord[tg][pos[c]++] = (unsigned char)t;
        }
#pragma unroll
        for (int c = 0; c < 4; c++)
            for (int i = cnt[c]; i < ((cnt[c] + 7) & ~7); i++)
                ord[tg][o[c] + i] = 128;               // dummy token
        it_cnt[tg] = o[4] >> 3;
#pragma unroll
        for (int c = 0; c < 5; c++) offp[tg][c] = (unsigned char)o[c];
    }
    __syncthreads();

    if (tid == 0) {
        int run = 0;
        for (int tg = 0; tg < NTG; tg++) { it_off[tg] = run; run += it_cnt[tg]; }
        it_off[NTG] = run;
    }
    __syncthreads();

    if (tid < NTG) {
        const int tg   = tid;
        const int base = it_off[tg];
        const int n    = it_cnt[tg];
        for (int i = 0; i < n; i++) {
            const int slot = i * 8;
            int cell = 3;
#pragma unroll
            for (int c = 0; c < 3; c++)
                if (slot < (int)offp[tg][c + 1]) { cell = c; break; }
            u64 tk = 0;
#pragma unroll
            for (int j = 0; j < 8; j++)
                tk |= (u64)ord[tg][slot + j] << (8 * j);
            s_itok[base + i]  = tk;
            s_imeta[base + i] = (u32)cell | ((u32)tg << 8);
        }
    }
    __syncthreads();

    const int total  = it_off[NTG];
    const int padded = (total + 15) & ~15;
    if (tid == 0) g_nit[blockIdx.x] = padded;
    for (int e = total + tid; e < padded; e += 128) {
        s_itok[e]  = 0x8080808080808080ull;            // all-dummy item
        s_imeta[e] = (31u << 8);                       // tg 31, cell 0
    }
    __syncthreads();
    for (int e = tid; e < padded; e += 128) {
        g_itok[blockIdx.x * MAXIT + e]  = s_itok[e];
        g_imeta[blockIdx.x * MAXIT + e] = s_imeta[e];
    }
}

// =============================================================================
// Kernel 3: selected affine apply.
// Grid (16 tiles, 8 oc-chunks of 64) x 128 thr.  Thread = (item tid>>3, oct
// tid&7): 8 same-cell tokens x 8 outs in registers.  4-deep cp.async ring of
// per-tg weight buffers (bias folded as row 32, z[32]=1).  smem acc, RMW races
// across the <=2 adjacent tgs of a round removed via tg-parity phases.
// smem layout (bytes):
//   w ring : 0      .. 143616   (4 bufs x WBUF f32)
//   z      : 143616 .. 161568   (33 x 136 f32)
//   acc    : 161568 .. 196656   (129 x 68 f32)
//   itok   : 196656 .. 201776
//   imeta  : 201776 .. 204336
// =============================================================================
#define SMEM_APPLY 204336

__global__ __launch_bounds__(128) void kApply(
    const float* __restrict__ aw, const float* __restrict__ ab,
    float* __restrict__ out) {
    extern __shared__ __align__(16) unsigned char sm[];
    float* w_s     = (float*)sm;
    float* z_s     = (float*)(sm + 143616);
    float* acc     = (float*)(sm + 161568);
    u64*   s_itok  = (u64*)(sm + 196656);
    u32*   s_imeta = (u32*)(sm + 201776);

    const int tid   = threadIdx.x;
    const int tile0 = blockIdx.x * TILE_TOK;
    const int oc    = blockIdx.y * OC;
    const int oct   = tid & 7;
    const u32 smb   = (u32)__cvta_generic_to_shared(sm);

    {   // stage z transposed [r][tok]; bias row 32 = 1; dummy cols zero
        const float4* zp = (const float4*)(g_z + (size_t)(tile0 + tid) * RANK);
#pragma unroll
        for (int j = 0; j < 8; j++) {
            const float4 v = zp[j];
            z_s[(4 * j + 0) * ZROW + tid] = v.x;
            z_s[(4 * j + 1) * ZROW + tid] = v.y;
            z_s[(4 * j + 2) * ZROW + tid] = v.z;
            z_s[(4 * j + 3) * ZROW + tid] = v.w;
        }
        z_s[32 * ZROW + tid] = 1.0f;
        if (tid < 8)
#pragma unroll
            for (int r = 0; r < 33; r++) z_s[r * ZROW + 128 + tid] = 0.f;
    }
    for (int e = tid; e < 129 * ACCS; e += 128) acc[e] = 0.f;
    const int nit = g_nit[blockIdx.x];
    for (int e = tid; e < nit; e += 128) {
        s_itok[e]  = g_itok[blockIdx.x * MAXIT + e];
        s_imeta[e] = g_imeta[blockIdx.x * MAXIT + e];
    }
    __syncthreads();

    int staged = 0;
    for (int base = 0; base < nit; base += 16) {
        const int lt  = (int)(s_imeta[base + 15] >> 8);   // last tg this round
        int tgt = lt + 3; if (tgt > NTG) tgt = NTG;
        while (staged < tgt) {                            // stage tg 'staged'
            const int s = staged, b = s & 3;
            for (int e = tid; e < 2112; e += 128) {       // 4 cells*33 rows*16 f4
                const int c = e / 528, rem = e - c * 528;
                const int r = rem >> 4, j = rem & 15;
                const float* src = (r < 32)
                    ? aw + (((size_t)(s * 4 + c) * RANK + r) * OUT_DIM + oc + j * 4)
                    : ab + ((size_t)(s * 4 + c) * OUT_DIM + oc + j * 4);
                const u32 dst = smb +
                    (u32)((b * WBUF + c * WCELL + r * WROW + j * 4) * 4);
                asm volatile("cp.async.ca.shared.global [%0], [%1], 16;"
                             :: "r"(dst), "l"(src));
            }
            asm volatile("cp.async.commit_group;" ::: "memory");
            staged++;
        }
        if (lt < 30)       asm volatile("cp.async.wait_group 2;" ::: "memory");
        else if (lt == 30) asm volatile("cp.async.wait_group 1;" ::: "memory");
        else               asm volatile("cp.async.wait_group 0;" ::: "memory");
        __syncthreads();

        // ---- compute this round's item ----
        const int it   = base + (tid >> 3);
        const u64 toks = s_itok[it];
        const u32 meta = s_imeta[it];
        const int cell = (int)(meta & 0xFFu);
        const int tg   = (int)(meta >> 8);
        const u32 wb   = smb +
            (u32)(((tg & 3) * WBUF + cell * WCELL) * 4) + (u32)(oct * 16);
        int t8[8];
#pragma unroll
        for (int j = 0; j < 8; j++) t8[j] = (int)((toks >> (8 * j)) & 0xFF);

        u64 a[32];
#pragma unroll
        for (int i = 0; i < 32; i++) a[i] = 0ull;

#pragma unroll 3
        for (int r = 0; r < 33; r++) {
            u64 w0x, w0y, w1x, w1y;
            asm("ld.shared.v2.b64 {%0, %1}, [%2];"
                : "=l"(w0x), "=l"(w0y) : "r"(wb + (u32)(r * 272)));
            asm("ld.shared.v2.b64 {%0, %1}, [%2];"
                : "=l"(w1x), "=l"(w1y) : "r"(wb + (u32)(r * 272 + 128)));
            const float* zrow = z_s + r * ZROW;
#pragma unroll
            for (int j = 0; j < 8; j++) {
                const u64 zd = dup2(zrow[t8[j]]);
                ffma2(a[4 * j + 0], zd, w0x);
                ffma2(a[4 * j + 1], zd, w0y);
                ffma2(a[4 * j + 2], zd, w1x);
                ffma2(a[4 * j + 3], zd, w1y);
            }
        }

        // ---- RMW acc in two tg-parity phases (round spans <=2 adjacent tgs) --
        if ((tg & 1) == 0) {
#pragma unroll
            for (int j = 0; j < 8; j++) {
                float* p = acc + t8[j] * ACCS + oct * 4;
                float4 c0 = *(float4*)p, c1 = *(float4*)(p + 32);
                const float2 x0 = u2f(a[4*j+0]), x1 = u2f(a[4*j+1]);
                const float2 x2 = u2f(a[4*j+2]), x3 = u2f(a[4*j+3]);
                c0.x += x0.x; c0.y += x0.y; c0.z += x1.x; c0.w += x1.y;
                c1.x += x2.x; c1.y += x2.y; c1.z += x3.x; c1.w += x3.y;
                *(float4*)p = c0; *(float4*)(p + 32) = c1;
            }
        }
        __syncthreads();
        if ((tg & 1) == 1) {
#pragma unroll
            for (int j = 0; j < 8; j++) {
                float* p = acc + t8[j] * ACCS + oct * 4;
                float4 c0 = *(float4*)p, c1 = *(float4*)(p + 32);
                const float2 x0 = u2f(a[4*j+0]), x1 = u2f(a[4*j+1]);
                const float2 x2 = u2f(a[4*j+2]), x3 = u2f(a[4*j+3]);
                c0.x += x0.x; c0.y += x0.y; c0.z += x1.x; c0.w += x1.y;
                c1.x += x2.x; c1.y += x2.y; c1.z += x3.x; c1.w += x3.y;
                *(float4*)p = c0; *(float4*)(p + 32) = c1;
            }
        }
        __syncthreads();
    }

    // ---- epilogue: scale + store (thread tid owns token row tid) ----
    const float S = 0.17677669529663687f;   // 1/sqrt(32)
    float* op = out + (size_t)(tile0 + tid) * OUT_DIM + oc;
    const float* ap = acc + tid * ACCS;
#pragma unroll
    for (int j = 0; j < 16; j++) {
        float4 v = *(const float4*)(ap + j * 4);
        v.x *= S; v.y *= S; v.z *= S; v.w *= S;
        ((float4*)op)[j] = v;
    }
}

// =============================================================================
extern "C" void kernel_launch(void* const* d_in, const int* in_sizes, int n_in,
                              void* d_out, int out_size) {
    const float* x   = (const float*)d_in[0];
    const float* pw  = (const float*)d_in[1];
    const float* rw  = (const float*)d_in[2];
    const float* rb  = (const float*)d_in[3];
    const float* aw  = (const float*)d_in[4];
    const float* ab  = (const float*)d_in[5];
    float*       out = (float*)d_out;

    cudaFuncSetAttribute(kApply, cudaFuncAttributeMaxDynamicSharedMemorySize,
                         SMEM_APPLY);

    kRoute<<<TOKENS / 4, 256>>>(x, pw, rw, rb);
    kSort<<<NTILE, 128>>>();
    kApply<<<dim3(NTILE, OUT_DIM / OC), 128, SMEM_APPLY>>>(aw, ab, out);
}

// round 6
// speedup vs baseline: 1.6186x; 1.0537x over previous
#include <cuda_runtime.h>
#include <cstdint>

typedef unsigned long long u64;
typedef unsigned int u32;

#define TOKENS   2048
#define IN_DIM   1024
#define OUT_DIM  512
#define RANK     32
#define NTG      32
#define NTILE    16
#define TILE_TOK 128
#define OC       64
#define MAXIT    640
#define WROW     68              // floats per weight row (64 + 4 pad)
#define WCELL    (33*WROW)       // 2244 floats per cell (32 w rows + bias row)
#define WBUF     (4*WCELL)       // 8976 floats per tg buffer
#define ZROW     136             // 128 tokens + 8 dummy cols
#define ACCS     68

// ---------------- scratch (static device globals: allocation-free) ----------
__device__ __align__(16) float         g_z[TOKENS * RANK];
__device__ __align__(16) unsigned char g_win[TOKENS * NTG];
__device__ __align__(16) u64           g_itok[NTILE * MAXIT];
__device__ u32                         g_imeta[NTILE * MAXIT];
__device__ int                         g_nit[NTILE];

// ---------------- helpers ----------------------------------------------------
__device__ __forceinline__ u64 dup2(float v) {
    u64 r; asm("mov.b64 %0, {%1, %1};" : "=l"(r) : "f"(v)); return r;
}
__device__ __forceinline__ void ffma2(u64& d, u64 a, u64 b) {
    asm("fma.rn.f32x2 %0, %1, %2, %0;" : "+l"(d) : "l"(a), "l"(b));
}
__device__ __forceinline__ float2 u2f(u64 v) {
    float2 r; asm("mov.b64 {%0, %1}, %2;" : "=f"(r.x), "=f"(r.y) : "l"(v)); return r;
}

// =============================================================================
// Kernel 1: z projection + routing argmin.
// 128 blocks x 256 thr x 16 tokens: 4x proj_w reuse vs R5, fma-bound.
// dyn smem: xs 65536 | rw_s 16512 | rb_s 512 | zs 2048  = 84608 B
// =============================================================================
#define SMEM_ROUTE 84608

__global__ __launch_bounds__(256) void kRoute(
    const float* __restrict__ x, const float* __restrict__ proj_w,
    const float* __restrict__ router_w, const float* __restrict__ router_b) {
    extern __shared__ __align__(16) unsigned char smr[];
    float* xs   = (float*)smr;                       // [16][1024]
    float* rw_s = (float*)(smr + 65536);             // [32][129]
    float* rb_s = (float*)(smr + 82048);             // [128]
    float* zs   = (float*)(smr + 82560);             // [16][32] == g_z slice

    const int tid  = threadIdx.x;
    const int tok0 = blockIdx.x * 16;

    {   // stage 16 token rows of x (coalesced float4)
        const float4* xg  = (const float4*)(x + (size_t)tok0 * IN_DIM);
        float4*       xs4 = (float4*)xs;
#pragma unroll
        for (int i = 0; i < 16; i++) xs4[tid + 256 * i] = xg[tid + 256 * i];
    }
    {   // stage router_w coalesced -> padded rows (stride 129, bank-safe)
#pragma unroll
        for (int e = tid; e < 1024; e += 256) {
            const float4 v = ((const float4*)router_w)[e];
            const int tg = e >> 5, w4 = e & 31;
            float* d = &rw_s[tg * 129 + (w4 >> 3) * 32 + (w4 & 7) * 4];
            d[0] = v.x; d[1] = v.y; d[2] = v.z; d[3] = v.w;
        }
        if (tid < 128) rb_s[tid] = router_b[tid];
    }
    __syncthreads();

    const int w = tid >> 5, lane = tid & 31;
    // warp w computes z rows 4w..4w+3 for all 16 tokens
    float acc[4][16];
#pragma unroll
    for (int j = 0; j < 4; j++)
#pragma unroll
        for (int t = 0; t < 16; t++) acc[j][t] = 0.f;

#pragma unroll 2
    for (int m = 0; m < 32; m++) {
        const int i = lane + 32 * m;
        float wv[4];
#pragma unroll
        for (int j = 0; j < 4; j++)
            wv[j] = __ldg(&proj_w[(size_t)(w * 4 + j) * IN_DIM + i]);
#pragma unroll
        for (int t = 0; t < 16; t++) {
            const float xv = xs[(t << 10) + i];
#pragma unroll
            for (int j = 0; j < 4; j++) acc[j][t] += wv[j] * xv;
        }
    }
#pragma unroll
    for (int j = 0; j < 4; j++)
#pragma unroll
        for (int t = 0; t < 16; t++) {
            float s = acc[j][t];
#pragma unroll
            for (int off = 16; off > 0; off >>= 1)
                s += __shfl_xor_sync(0xffffffffu, s, off);
            if (lane == 0) zs[t * 32 + w * 4 + j] = s;
        }
    __syncthreads();

    // dump z coalesced (zs layout == g_z row-major slice)
    if (tid < 128)
        ((float4*)(g_z + (size_t)tok0 * RANK))[tid] = ((const float4*)zs)[tid];

    // scores (fp32): unit u = (token t, tg); 512 units over 256 thr.
#pragma unroll
    for (int p = 0; p < 2; p++) {
        const int u  = tid + 256 * p;
        const int t  = u >> 5;
        const int tg = u & 31;
        float s[4];
#pragma unroll
        for (int k = 0; k < 4; k++) s[k] = rb_s[tg * 4 + k];
#pragma unroll 8
        for (int r = 0; r < RANK; r++) {
            const float zr = zs[t * 32 + r];
#pragma unroll
            for (int k = 0; k < 4; k++) s[k] += zr * rw_s[tg * 129 + k * 32 + r];
        }
        int best = 0; float bv = s[0];
#pragma unroll
        for (int k = 1; k < 4; k++)
            if (s[k] < bv) { bv = s[k]; best = k; }
        g_win[(size_t)(tok0 + t) * NTG + tg] = (unsigned char)best;
    }
}

// =============================================================================
// Kernel 2: per-tile cell sort -> flat item list (tg-ordered).
// 16 blocks x 128 thr.  Item = 8 same-cell tokens (u64) + meta (cell | tg<<8).
// Dummy token = 128 pads cells to 8; items/tg in [16,19]; rounds padded to 32.
// =============================================================================
__global__ __launch_bounds__(128) void kSort() {
    __shared__ unsigned char win_t[NTG][132];
    __shared__ unsigned char ord[NTG][160];
    __shared__ unsigned char offp[NTG][5];
    __shared__ int it_cnt[NTG];
    __shared__ int it_off[NTG + 1];
    __shared__ u64 s_itok[MAXIT];
    __shared__ u32 s_imeta[MAXIT];

    const int tid   = threadIdx.x;
    const int tile0 = blockIdx.x * TILE_TOK;

    {   // transpose win: [tok][tg] -> win_t[tg][tok]
        const u32* wp = (const u32*)(g_win + (size_t)(tile0 + tid) * NTG);
#pragma unroll
        for (int q = 0; q < 8; q++) {
            const u32 v = wp[q];
            win_t[q * 4 + 0][tid] = (unsigned char)(v);
            win_t[q * 4 + 1][tid] = (unsigned char)(v >> 8);
            win_t[q * 4 + 2][tid] = (unsigned char)(v >> 16);
            win_t[q * 4 + 3][tid] = (unsigned char)(v >> 24);
        }
    }
    __syncthreads();

    if (tid < NTG) {
        const int tg = tid;
        int cnt[4] = {0, 0, 0, 0};
        for (int t = 0; t < TILE_TOK; t++) cnt[win_t[tg][t]]++;
        int o[5]; o[0] = 0;
#pragma unroll
        for (int c = 0; c < 4; c++) o[c + 1] = o[c] + ((cnt[c] + 7) & ~7);
        int pos[4];
#pragma unroll
        for (int c = 0; c < 4; c++) pos[c] = o[c];
        for (int t = 0; t < TILE_TOK; t++) {
            const int c = win_t[tg][t];
            ord[tg][pos[c]++] = (unsigned char)t;
        }
#pragma unroll
        for (int c = 0; c < 4; c++)
            for (int i = cnt[c]; i < ((cnt[c] + 7) & ~7); i++)
                ord[tg][o[c] + i] = 128;               // dummy token
        it_cnt[tg] = o[4] >> 3;
#pragma unroll
        for (int c = 0; c < 5; c++) offp[tg][c] = (unsigned char)o[c];
    }
    __syncthreads();

    if (tid == 0) {
        int run = 0;
        for (int tg = 0; tg < NTG; tg++) { it_off[tg] = run; run += it_cnt[tg]; }
        it_off[NTG] = run;
    }
    __syncthreads();

    if (tid < NTG) {
        const int tg   = tid;
        const int base = it_off[tg];
        const int n    = it_cnt[tg];
        for (int i = 0; i < n; i++) {
            const int slot = i * 8;
            int cell = 3;
#pragma unroll
            for (int c = 0; c < 3; c++)
                if (slot < (int)offp[tg][c + 1]) { cell = c; break; }
            u64 tk = 0;
#pragma unroll
            for (int j = 0; j < 8; j++)
                tk |= (u64)ord[tg][slot + j] << (8 * j);
            s_itok[base + i]  = tk;
            s_imeta[base + i] = (u32)cell | ((u32)tg << 8);
        }
    }
    __syncthreads();

    const int total  = it_off[NTG];
    const int padded = (total + 31) & ~31;             // 32-item rounds
    if (tid == 0) g_nit[blockIdx.x] = padded;
    for (int e = total + tid; e < padded; e += 128) {
        s_itok[e]  = 0x8080808080808080ull;            // all-dummy item
        s_imeta[e] = (31u << 8);                       // tg 31, cell 0
    }
    __syncthreads();
    for (int e = tid; e < padded; e += 128) {
        g_itok[blockIdx.x * MAXIT + e]  = s_itok[e];
        g_imeta[blockIdx.x * MAXIT + e] = s_imeta[e];
    }
}

// =============================================================================
// Kernel 3: selected affine apply.
// Grid (16 tiles, 8 oc-chunks of 64) x 256 thr.  Round = 32 items; thread =
// (item tid>>3, oct tid&7): 8 same-cell tokens x 8 outs in registers.
// 4-deep cp.async ring of per-tg weight buffers (bias folded as row 32,
// z[32]=1); prefetch exactly 1 tg ahead (live window {lt-2..lt+1} = 4 bufs).
// Round spans <= 3 adjacent tgs -> RMW race-free via tg mod 3 phases.
// smem layout (bytes):
//   w ring : 0      .. 143616   (4 bufs x WBUF f32)
//   z      : 143616 .. 161568   (33 x 136 f32)
//   acc    : 161568 .. 196656   (129 x 68 f32)
//   itok   : 196656 .. 201776
//   imeta  : 201776 .. 204336
// =============================================================================
#define SMEM_APPLY 204336

__global__ __launch_bounds__(256) void kApply(
    const float* __restrict__ aw, const float* __restrict__ ab,
    float* __restrict__ out) {
    extern __shared__ __align__(16) unsigned char sm[];
    float* z_s     = (float*)(sm + 143616);
    float* acc     = (float*)(sm + 161568);
    u64*   s_itok  = (u64*)(sm + 196656);
    u32*   s_imeta = (u32*)(sm + 201776);

    const int tid   = threadIdx.x;
    const int tile0 = blockIdx.x * TILE_TOK;
    const int oc    = blockIdx.y * OC;
    const int oct   = tid & 7;
    const u32 smb   = (u32)__cvta_generic_to_shared(sm);
    const u32 accb  = smb + 161568;

    if (tid < 128) {   // stage z transposed [r][tok]; bias row = 1; dummies 0
        const float4* zp = (const float4*)(g_z + (size_t)(tile0 + tid) * RANK);
#pragma unroll
        for (int j = 0; j < 8; j++) {
            const float4 v = zp[j];
            z_s[(4 * j + 0) * ZROW + tid] = v.x;
            z_s[(4 * j + 1) * ZROW + tid] = v.y;
            z_s[(4 * j + 2) * ZROW + tid] = v.z;
            z_s[(4 * j + 3) * ZROW + tid] = v.w;
        }
        z_s[32 * ZROW + tid] = 1.0f;
        if (tid < 8)
#pragma unroll
            for (int r = 0; r < 33; r++) z_s[r * ZROW + 128 + tid] = 0.f;
    }
    for (int e = tid; e < 129 * ACCS; e += 256) acc[e] = 0.f;
    const int nit = g_nit[blockIdx.x];
    for (int e = tid; e < nit; e += 256) {
        s_itok[e]  = g_itok[blockIdx.x * MAXIT + e];
        s_imeta[e] = g_imeta[blockIdx.x * MAXIT + e];
    }
    __syncthreads();

    int staged = 0;
    for (int base = 0; base < nit; base += 32) {
        const int lt  = (int)(s_imeta[base + 31] >> 8);   // last tg this round
        int tgt = lt + 2; if (tgt > NTG) tgt = NTG;
        while (staged < tgt) {                            // stage tg 'staged'
            const int s = staged, b = s & 3;
            for (int e = tid; e < 2112; e += 256) {       // 4 cells*33 r*16 f4
                const int c = e / 528, rem = e - c * 528;
                const int r = rem >> 4, j = rem & 15;
                const float* src = (r < 32)
                    ? aw + (((size_t)(s * 4 + c) * RANK + r) * OUT_DIM + oc + j * 4)
                    : ab + ((size_t)(s * 4 + c) * OUT_DIM + oc + j * 4);
                const u32 dst = smb +
                    (u32)((b * WBUF + c * WCELL + r * WROW + j * 4) * 4);
                asm volatile("cp.async.ca.shared.global [%0], [%1], 16;"
                             :: "r"(dst), "l"(src));
            }
            asm volatile("cp.async.commit_group;" ::: "memory");
            staged++;
        }
        if (staged > lt + 1) asm volatile("cp.async.wait_group 1;" ::: "memory");
        else                 asm volatile("cp.async.wait_group 0;" ::: "memory");
        __syncthreads();

        // ---- compute this round's item ----
        const int it   = base + (tid >> 3);
        const u64 toks = s_itok[it];
        const u32 meta = s_imeta[it];
        const int cell = (int)(meta & 0xFFu);
        const int tg   = (int)(meta >> 8);
        const u32 wb   = smb +
            (u32)(((tg & 3) * WBUF + cell * WCELL) * 4) + (u32)(oct * 16);
        int t8[8];
#pragma unroll
        for (int j = 0; j < 8; j++) t8[j] = (int)((toks >> (8 * j)) & 0xFF);

        u64 a[32];
#pragma unroll
        for (int i = 0; i < 32; i++) a[i] = 0ull;

#pragma unroll 3
        for (int r = 0; r < 33; r++) {
            u64 w0x, w0y, w1x, w1y;
            asm("ld.shared.v2.b64 {%0, %1}, [%2];"
                : "=l"(w0x), "=l"(w0y) : "r"(wb + (u32)(r * 272)));
            asm("ld.shared.v2.b64 {%0, %1}, [%2];"
                : "=l"(w1x), "=l"(w1y) : "r"(wb + (u32)(r * 272 + 128)));
            const float* zrow = z_s + r * ZROW;
#pragma unroll
            for (int j = 0; j < 8; j++) {
                const u64 zd = dup2(zrow[t8[j]]);
                ffma2(a[4 * j + 0], zd, w0x);
                ffma2(a[4 * j + 1], zd, w0y);
                ffma2(a[4 * j + 2], zd, w1x);
                ffma2(a[4 * j + 3], zd, w1y);
            }
        }

        // ---- RMW acc in 3 tg-mod-3 phases (round spans <=3 adjacent tgs) ----
        const int myph = tg - (tg / 3) * 3;
#pragma unroll
        for (int ph = 0; ph < 3; ph++) {
            if (myph == ph) {
#pragma unroll
                for (int j = 0; j < 8; j++) {
                    const u32 p = accb + (u32)(t8[j] * (ACCS * 4) + oct * 16);
                    u64 c0, c1, c2, c3;
                    asm("ld.shared.v2.b64 {%0, %1}, [%2];"
                        : "=l"(c0), "=l"(c1) : "r"(p));
                    asm("ld.shared.v2.b64 {%0, %1}, [%2];"
                        : "=l"(c2), "=l"(c3) : "r"(p + 128));
                    asm("add.rn.f32x2 %0, %0, %1;" : "+l"(c0) : "l"(a[4*j+0]));
                    asm("add.rn.f32x2 %0, %0, %1;" : "+l"(c1) : "l"(a[4*j+1]));
                    asm("add.rn.f32x2 %0, %0, %1;" : "+l"(c2) : "l"(a[4*j+2]));
                    asm("add.rn.f32x2 %0, %0, %1;" : "+l"(c3) : "l"(a[4*j+3]));
                    asm volatile("st.shared.v2.b64 [%0], {%1, %2};"
                                 :: "r"(p), "l"(c0), "l"(c1));
                    asm volatile("st.shared.v2.b64 [%0], {%1, %2};"
                                 :: "r"(p + 128), "l"(c2), "l"(c3));
                }
            }
            __syncthreads();
        }
    }

    // ---- epilogue: scale + store (2048 float4 over 256 thr) ----
    const float S = 0.17677669529663687f;   // 1/sqrt(32)
    for (int e = tid; e < TILE_TOK * (OC / 4); e += 256) {
        const int tk = e >> 4, o4 = e & 15;
        float4 v = *(const float4*)(acc + tk * ACCS + o4 * 4);
        v.x *= S; v.y *= S; v.z *= S; v.w *= S;
        ((float4*)(out + (size_t)(tile0 + tk) * OUT_DIM + oc))[o4] = v;
    }
}

// =============================================================================
extern "C" void kernel_launch(void* const* d_in, const int* in_sizes, int n_in,
                              void* d_out, int out_size) {
    const float* x   = (const float*)d_in[0];
    const float* pw  = (const float*)d_in[1];
    const float* rw  = (const float*)d_in[2];
    const float* rb  = (const float*)d_in[3];
    const float* aw  = (const float*)d_in[4];
    const float* ab  = (const float*)d_in[5];
    float*       out = (float*)d_out;

    cudaFuncSetAttribute(kRoute, cudaFuncAttributeMaxDynamicSharedMemorySize,
                         SMEM_ROUTE);
    cudaFuncSetAttribute(kApply, cudaFuncAttributeMaxDynamicSharedMemorySize,
                         SMEM_APPLY);

    kRoute<<<TOKENS / 16, 256, SMEM_ROUTE>>>(x, pw, rw, rb);
    kSort<<<NTILE, 128>>>();
    kApply<<<dim3(NTILE, OUT_DIM / OC), 256, SMEM_APPLY>>>(aw, ab, out);
}